// round 11
// baseline (speedup 1.0000x reference)
#include <cuda_runtime.h>

// Problem constants
#define BATCH   4
#define NPTS    16384
#define HALF    8192
#define FDIM    32
#define GD      16               // cells per axis (in CDF/u-space)
#define NC      (GD*GD*GD)       // 4096 cells per batch
#define NG      512              // 8x8x8 query groups per batch
#define CAP     768              // staged-candidate capacity per block

typedef unsigned int u32;
typedef unsigned long long u64;

// Output layout (concatenated tuple, float32)
#define OFF_VPC   0
#define OFF_VFEAT (BATCH * HALF * 3)                  // 98304
#define OFF_NIDX  (OFF_VFEAT + BATCH * HALF * FDIM)   // 1146880
#define OFF_RNDS  (OFF_NIDX + BATCH * HALF)           // 1179648

// Cell boundaries in x-space: standard normal quantiles Phi^-1(i/16).
__constant__ float c_bnd[GD + 1] = {
    -1e30f,
    -1.5341206f, -1.1503494f, -0.8871466f, -0.6744898f,
    -0.4887764f, -0.3186394f, -0.1573107f,  0.0f,
     0.1573107f,  0.3186394f,  0.4887764f,  0.6744898f,
     0.8871466f,  1.1503494f,  1.5341206f,
     1e30f
};

// ---------------------------------------------------------------------------
// Scratch (device globals; no allocation allowed)
// ---------------------------------------------------------------------------
__device__ float4 g_valid[BATCH][HALF];   // (2x,2y,2z,p2) original order
__device__ float4 g_query[BATCH][HALF];
__device__ int    g_pcell[BATCH][HALF];   // point cell id (16^3)
__device__ int    g_qgrp[BATCH][HALF];    // query group id (8^3)
__device__ int    g_pcnt[BATCH][NC];
__device__ int    g_qcnt[BATCH][NG];
__device__ int    g_poff[BATCH][NC + 1];
__device__ int    g_qoff[BATCH][NG + 1];
__device__ int    g_pcur[BATCH][NC];
__device__ int    g_qcur[BATCH][NG];
__device__ float4 g_spt[BATCH][HALF];     // cell-sorted points
__device__ int    g_sid[BATCH][HALF];     // original point index
__device__ float4 g_sq[BATCH][HALF];      // group-sorted queries
__device__ int    g_sqid[BATCH][HALF];

// ||v||^2 left-to-right, no FMA contraction (match jax fp32 semantics)
__device__ __forceinline__ float sq3(float x, float y, float z) {
    return __fadd_rn(__fadd_rn(__fmul_rn(x, x), __fmul_rn(y, y)), __fmul_rn(z, z));
}

__device__ __forceinline__ int axis_cell(float x) {
    float u = __fmaf_rn(erff(x * 0.70710678f), 0.5f, 0.5f);
    int c = (int)(u * (float)GD);
    return max(0, min(GD - 1, c));
}

// Order-preserving float->u32 encode
__device__ __forceinline__ u32 fenc32(float f) {
    u32 u = __float_as_uint(f);
    return u ^ ((u32)((int)u >> 31) | 0x80000000u);
}
__device__ __forceinline__ float fdec32(u32 e) {
    u32 u = (e & 0x80000000u) ? (e ^ 0x80000000u) : ~e;
    return __uint_as_float(u);
}

// Key = (enc(d2) << 32) | id : u64 order == stable top_k comparator.
// Same id => identical key (deterministic formula) => dedup = key equality.
#define KINF (((u64)0xFF800000u << 32) | 0xFFFFFFFFu)

__device__ __forceinline__ void ins2k(u64 k, u64& k1, u64& k2) {
    if (k == k1 || k == k2) return;
    if (k < k1) { k2 = k1; k1 = k; }
    else if (k < k2) { k2 = k; }
}

__device__ __forceinline__ void warp_reduce_top2k(u64& k1, u64& k2) {
    u64 k1g = k1;
#pragma unroll
    for (int o = 16; o > 0; o >>= 1)
        k1g = min(k1g, __shfl_xor_sync(0xFFFFFFFFu, k1g, o));
    u64 cand = (k1 == k1g) ? k2 : k1;
#pragma unroll
    for (int o = 16; o > 0; o >>= 1)
        cand = min(cand, __shfl_xor_sync(0xFFFFFFFFu, cand, o));
    k1 = k1g; k2 = cand;
}

// exact reference-rounded candidate scoring
__device__ __forceinline__ float score(float qx, float qy, float qz, float q2,
                                       float4 P) {
    float dot2 = __fadd_rn(__fadd_rn(__fmul_rn(qx, P.x), __fmul_rn(qy, P.y)),
                           __fmul_rn(qz, P.z));
    return __fsub_rn(__fadd_rn(q2, P.w), dot2);
}

// ---------------------------------------------------------------------------
// K0: zero histograms
// ---------------------------------------------------------------------------
__global__ void init_kernel() {
    int i = blockIdx.x * blockDim.x + threadIdx.x;
    if (i < BATCH * NC) ((int*)g_pcnt)[i] = 0;
    if (i < BATCH * NG) ((int*)g_qcnt)[i] = 0;
}

// ---------------------------------------------------------------------------
// K1: gathers + binning + histogram (points by cell, queries by 2x2x2 group)
// ---------------------------------------------------------------------------
__global__ void gather_kernel(const float* __restrict__ pc,
                              const float4* __restrict__ feats4,
                              const int* __restrict__ rnds,
                              float* __restrict__ out) {
    int i = blockIdx.x * blockDim.x + threadIdx.x;
    const int WF = BATCH * HALF * 8;
    const int WP = BATCH * HALF;

    if (i < WF) {
        int c = i & 7;
        int t = (i >> 3) & (HALF - 1);
        int b = i >> 16;
        int v = rnds[t];
        float4 val = feats4[(b * NPTS + v) * 8 + c];
        ((float4*)(out + OFF_VFEAT))[(b * HALF + t) * 8 + c] = val;
        return;
    }
    i -= WF;
    if (i < WP) {
        int t = i & (HALF - 1);
        int b = i >> 13;
        int v = rnds[t];
        int base = (b * NPTS + v) * 3;
        float x = pc[base + 0], y = pc[base + 1], z = pc[base + 2];
        int ob = OFF_VPC + (b * HALF + t) * 3;
        out[ob + 0] = x; out[ob + 1] = y; out[ob + 2] = z;
        g_valid[b][t] = make_float4(2.0f * x, 2.0f * y, 2.0f * z, sq3(x, y, z));
        int cid = (axis_cell(z) * GD + axis_cell(y)) * GD + axis_cell(x);
        g_pcell[b][t] = cid;
        atomicAdd(&g_pcnt[b][cid], 1);
        return;
    }
    i -= WP;
    if (i < WP) {
        int t = i & (HALF - 1);
        int b = i >> 13;
        int v = rnds[HALF + t];
        int base = (b * NPTS + v) * 3;
        float x = pc[base + 0], y = pc[base + 1], z = pc[base + 2];
        g_query[b][t] = make_float4(x, y, z, sq3(x, y, z));
        int gid = ((axis_cell(z) >> 1) * 8 + (axis_cell(y) >> 1)) * 8 +
                  (axis_cell(x) >> 1);
        g_qgrp[b][t] = gid;
        atomicAdd(&g_qcnt[b][gid], 1);
        return;
    }
    i -= WP;
    if (i < NPTS) out[OFF_RNDS + i] = (float)rnds[i];
}

// ---------------------------------------------------------------------------
// K2: exclusive scans. Blocks 0..3: point cells (4096). Blocks 4..7: query
// groups (512). Two-level warp shuffle scan, 2 syncthreads.
// ---------------------------------------------------------------------------
__global__ void __launch_bounds__(1024) scan_kernel() {
    int tid = threadIdx.x;
    int lane = tid & 31;
    int wid = tid >> 5;
    __shared__ int wsum[32];

    if (blockIdx.x < 4) {
        int b = blockIdx.x;
        const int CPT = NC / 1024;  // 4
        int loc[CPT];
        int s = 0;
        const int* cnt = g_pcnt[b];
#pragma unroll
        for (int j = 0; j < CPT; ++j) { loc[j] = s; s += cnt[tid * CPT + j]; }

        int inc = s;
#pragma unroll
        for (int o = 1; o < 32; o <<= 1) {
            int v = __shfl_up_sync(0xFFFFFFFFu, inc, o);
            if (lane >= o) inc += v;
        }
        if (lane == 31) wsum[wid] = inc;
        __syncthreads();
        if (wid == 0) {
            int v = wsum[lane];
            int wi = v;
#pragma unroll
            for (int o = 1; o < 32; o <<= 1) {
                int u = __shfl_up_sync(0xFFFFFFFFu, wi, o);
                if (lane >= o) wi += u;
            }
            wsum[lane] = wi - v;
        }
        __syncthreads();
        int base = wsum[wid] + (inc - s);
#pragma unroll
        for (int j = 0; j < CPT; ++j) {
            int v = base + loc[j];
            g_poff[b][tid * CPT + j] = v;
            g_pcur[b][tid * CPT + j] = v;
        }
        if (tid == 1023) g_poff[b][NC] = base + s;
    } else {
        int b = blockIdx.x - 4;
        int s = (tid < NG) ? g_qcnt[b][tid] : 0;
        int inc = s;
#pragma unroll
        for (int o = 1; o < 32; o <<= 1) {
            int v = __shfl_up_sync(0xFFFFFFFFu, inc, o);
            if (lane >= o) inc += v;
        }
        if (lane == 31) wsum[wid] = inc;
        __syncthreads();
        if (wid == 0) {
            int v = wsum[lane];
            int wi = v;
#pragma unroll
            for (int o = 1; o < 32; o <<= 1) {
                int u = __shfl_up_sync(0xFFFFFFFFu, wi, o);
                if (lane >= o) wi += u;
            }
            wsum[lane] = wi - v;
        }
        __syncthreads();
        int base = wsum[wid] + (inc - s);
        if (tid < NG) {
            g_qoff[b][tid] = base;
            g_qcur[b][tid] = base;
        }
        if (tid == NG - 1) g_qoff[b][NG] = base + s;
    }
}

// ---------------------------------------------------------------------------
// K3: scatter into sorted order
// ---------------------------------------------------------------------------
__global__ void scatter_kernel() {
    int i = blockIdx.x * blockDim.x + threadIdx.x;
    if (i >= 2 * BATCH * HALF) return;
    int kind = i >> 15;
    int b = (i >> 13) & (BATCH - 1);
    int t = i & (HALF - 1);
    if (kind == 0) {
        int cid = g_pcell[b][t];
        int pos = atomicAdd(&g_pcur[b][cid], 1);
        g_spt[b][pos] = g_valid[b][t];
        g_sid[b][pos] = t;
    } else {
        int gid = g_qgrp[b][t];
        int pos = atomicAdd(&g_qcur[b][gid], 1);
        g_sq[b][pos] = g_query[b][t];
        g_sqid[b][pos] = t;
    }
}

// ---------------------------------------------------------------------------
// K4: block-per-group KNN with smem candidate staging.
// One block = one 2x2x2-cell query group (~16 queries). The block stages all
// points of the surrounding 6x6x6-cell window (<=36 contiguous runs) into
// smem once, then each warp processes queries round-robin: lanes stride the
// staged list (LDS, no shuffles in the scan loop), one u64 top-2 reduce per
// query. Queries sit >= 2 cell-widths from every non-clamped window face =>
// termination ~always passes; failures (or smem overflow) fall back to
// warp-parallel global brute force (superset-safe). All scoring uses the
// exact reference-rounded formula; u64 key order == stable top_k comparator
// => bit-identical result.
// NOTE: run-length scan goes through smem (s_len) so warp 0's shuffles are
// fully convergent — a lane-conditional __shfl_sync deadlocked Round 10.
// ---------------------------------------------------------------------------
__global__ void __launch_bounds__(256) knn_kernel(float* __restrict__ out) {
    __shared__ float4 s_pts[CAP];
    __shared__ int    s_ids[CAP];
    __shared__ int    s_p0[40], s_len[40], s_dst[40];
    __shared__ int    s_T;   // staged count, or -1 on overflow

    int tid = threadIdx.x;
    int lane = tid & 31;
    int warpid = tid >> 5;

    int b = blockIdx.x >> 9;
    int g = blockIdx.x & (NG - 1);
    int gx = g & 7, gy = (g >> 3) & 7, gz = g >> 6;

    int bx0 = max(2 * gx - 2, 0), bx1 = min(2 * gx + 3, GD - 1);
    int by0 = max(2 * gy - 2, 0), by1 = min(2 * gy + 3, GD - 1);
    int bz0 = max(2 * gz - 2, 0), bz1 = min(2 * gz + 3, GD - 1);
    int NYR = by1 - by0 + 1;
    int NR = NYR * (bz1 - bz0 + 1);          // <= 36

    const float4* __restrict__ pts = g_spt[b];
    const int* __restrict__ ids = g_sid[b];
    const int* __restrict__ offs = g_poff[b];

    // run extents -> smem (threads 0..NR-1, may span warps 0 and 1)
    if (tid < NR) {
        int cy = by0 + tid % NYR;
        int cz = bz0 + tid / NYR;
        int rowbase = (cz * GD + cy) * GD;
        int p0 = __ldg(&offs[rowbase + bx0]);
        s_p0[tid] = p0;
        s_len[tid] = __ldg(&offs[rowbase + bx1 + 1]) - p0;
    }
    __syncthreads();

    // warp 0: fully-convergent scans of s_len[0..31] and s_len[32..NR)
    if (warpid == 0) {
        int l0 = (lane < NR) ? s_len[lane] : 0;             // LDS, no collective
        int idx2 = lane + 32;
        int l1 = (idx2 < NR) ? s_len[idx2] : 0;

        int inc = l0;
#pragma unroll
        for (int o = 1; o < 32; o <<= 1) {
            int v = __shfl_up_sync(0xFFFFFFFFu, inc, o);
            if (lane >= o) inc += v;
        }
        int tot0 = __shfl_sync(0xFFFFFFFFu, inc, 31);

        int inc1 = l1;
#pragma unroll
        for (int o = 1; o < 32; o <<= 1) {
            int v = __shfl_up_sync(0xFFFFFFFFu, inc1, o);
            if (lane >= o) inc1 += v;
        }
        int tot1 = __shfl_sync(0xFFFFFFFFu, inc1, 31);

        if (lane < NR) s_dst[lane] = inc - l0;
        if (idx2 < NR) s_dst[idx2] = tot0 + inc1 - l1;
        if (lane == 0) {
            int total = tot0 + tot1;
            s_T = (total <= CAP) ? total : -1;
        }
    }
    __syncthreads();

    int T = s_T;
    if (T > 0) {
        // staging copy: warps take runs round-robin; lanes stride each run
        for (int r = warpid; r < NR; r += 8) {
            int p0 = s_p0[r];
            int d = s_dst[r];
            int L = ((r + 1 < NR) ? s_dst[r + 1] : T) - d;
            for (int j = lane; j < L; j += 32) {
                s_pts[d + j] = pts[p0 + j];
                s_ids[d + j] = ids[p0 + j];
            }
        }
    }
    __syncthreads();

    // queries of this group
    int q0 = __ldg(&g_qoff[b][g]);
    int qn = __ldg(&g_qoff[b][g + 1]) - q0;

    for (int j = warpid; j < qn; j += 8) {
        int s = q0 + j;
        float4 q = g_sq[b][s];     // warp-broadcast load
        int qi = g_sqid[b][s];
        const float qx = q.x, qy = q.y, qz = q.z, q2 = q.w;

        u64 k1 = KINF, k2 = KINF;
        bool done = false;

        if (T > 0) {
            u32 b2hi = 0xFF800000u;
            for (int f = lane; f < T; f += 32) {
                float4 P = s_pts[f];
                u32 encd = fenc32(score(qx, qy, qz, q2, P));
                if (encd <= b2hi) {
                    ins2k(((u64)encd << 32) | (u32)s_ids[f], k1, k2);
                    b2hi = (u32)(k2 >> 32);
                }
            }
            warp_reduce_top2k(k1, k2);

            // termination: distance to non-clamped window faces
            float bd2 = fdec32((u32)(k2 >> 32));
            const float INF = __int_as_float(0x7f800000);
            if (bd2 < INF) {
                float lb = INF;
                if (bx0 > 0)      lb = fminf(lb, qx - c_bnd[bx0]);
                if (bx1 < GD - 1) lb = fminf(lb, c_bnd[bx1 + 1] - qx);
                if (by0 > 0)      lb = fminf(lb, qy - c_bnd[by0]);
                if (by1 < GD - 1) lb = fminf(lb, c_bnd[by1 + 1] - qy);
                if (bz0 > 0)      lb = fminf(lb, qz - c_bnd[bz0]);
                if (bz1 < GD - 1) lb = fminf(lb, c_bnd[bz1 + 1] - qz);
                float lba = fmaxf(lb - 1e-5f, 0.0f);
                done = lba * lba > bd2 * 1.001f + 1e-4f;
            }
        }

        if (!done) {
            // bounded fallback: warp-parallel brute force over all points
            u32 b2hi = (u32)(k2 >> 32);
            for (int p = lane; p < HALF; p += 32) {
                u32 encd = fenc32(score(qx, qy, qz, q2, pts[p]));
                if (encd <= b2hi) {
                    ins2k(((u64)encd << 32) | (u32)ids[p], k1, k2);
                    b2hi = (u32)(k2 >> 32);
                }
            }
            warp_reduce_top2k(k1, k2);
        }

        if (lane == 0)
            out[OFF_NIDX + (b << 13) + qi] = (float)(int)(u32)(k2 & 0xFFFFFFFFu);
    }
}

// ---------------------------------------------------------------------------
extern "C" void kernel_launch(void* const* d_in, const int* in_sizes, int n_in,
                              void* d_out, int out_size) {
    const float*  pc    = (const float*)d_in[0];
    const float4* feats = (const float4*)d_in[1];
    const int*    rnds  = (const int*)d_in[2];
    float*        out   = (float*)d_out;
    (void)in_sizes; (void)n_in; (void)out_size;

    init_kernel<<<(BATCH * NC + 255) / 256, 256>>>();

    const int total = BATCH * HALF * 8 + 2 * BATCH * HALF + NPTS;  // 344064
    gather_kernel<<<total / 256, 256>>>(pc, feats, rnds, out);

    scan_kernel<<<8, 1024>>>();
    scatter_kernel<<<(2 * BATCH * HALF + 255) / 256, 256>>>();

    // one block per (batch, 2x2x2-cell group)
    knn_kernel<<<BATCH * NG, 256>>>(out);
}

// round 12
// speedup vs baseline: 1.5630x; 1.5630x over previous
#include <cuda_runtime.h>

// Problem constants
#define BATCH   4
#define NPTS    16384
#define HALF    8192
#define FDIM    32
#define GD      16               // cells per axis (in CDF/u-space)
#define NC      (GD*GD*GD)       // 4096 cells per batch

// Output layout (concatenated tuple, float32)
#define OFF_VPC   0
#define OFF_VFEAT (BATCH * HALF * 3)                  // 98304
#define OFF_NIDX  (OFF_VFEAT + BATCH * HALF * FDIM)   // 1146880
#define OFF_RNDS  (OFF_NIDX + BATCH * HALF)           // 1179648

// Cell boundaries in x-space: standard normal quantiles Phi^-1(i/16).
__constant__ float c_bnd[GD + 1] = {
    -1e30f,
    -1.5341206f, -1.1503494f, -0.8871466f, -0.6744898f,
    -0.4887764f, -0.3186394f, -0.1573107f,  0.0f,
     0.1573107f,  0.3186394f,  0.4887764f,  0.6744898f,
     0.8871466f,  1.1503494f,  1.5341206f,
     1e30f
};

// ---------------------------------------------------------------------------
// Scratch (device globals; no allocation allowed). Zero-initialized at module
// load; g_cnt is re-zeroed by knn_kernel's tail each run (graph replays).
// ---------------------------------------------------------------------------
__device__ float4 g_valid[BATCH][HALF];
__device__ float4 g_query[BATCH][HALF];
__device__ int    g_pcell[BATCH][HALF];
__device__ int    g_qcell[BATCH][HALF];
__device__ int    g_cnt[2][BATCH][NC];
__device__ int    g_off[2][BATCH][NC+1];
__device__ int    g_cur[2][BATCH][NC];
__device__ float4 g_spt[BATCH][HALF];     // cell-sorted points (2x,2y,2z,p2)
__device__ int    g_sid[BATCH][HALF];     // original point index
__device__ float4 g_sq[BATCH][HALF];      // cell-sorted queries (x,y,z,q2)
__device__ int    g_sqid[BATCH][HALF];
__device__ int    g_sqc[BATCH][HALF];

// ||v||^2 left-to-right, no FMA contraction (match jax fp32 semantics)
__device__ __forceinline__ float sq3(float x, float y, float z) {
    return __fadd_rn(__fadd_rn(__fmul_rn(x, x), __fmul_rn(y, y)), __fmul_rn(z, z));
}

__device__ __forceinline__ int axis_cell(float x) {
    float u = __fmaf_rn(erff(x * 0.70710678f), 0.5f, 0.5f);
    int c = (int)(u * (float)GD);
    return max(0, min(GD - 1, c));
}
__device__ __forceinline__ int cell_of(float x, float y, float z) {
    return (axis_cell(z) * GD + axis_cell(y)) * GD + axis_cell(x);
}

__device__ __forceinline__ bool lt2(float d, int i, float e, int j) {
    return d < e || (d == e && i < j);
}

// Insert candidate (d, i) into sorted top-2 state, deduping by id.
__device__ __forceinline__ void ins2(float d, int i,
                                     float& bd1, int& bi1,
                                     float& bd2, int& bi2) {
    if (i == bi1 || i == bi2) return;
    if (lt2(d, i, bd1, bi1)) {
        bd2 = bd1; bi2 = bi1; bd1 = d; bi1 = i;
    } else if (lt2(d, i, bd2, bi2)) {
        bd2 = d; bi2 = i;
    }
}

__device__ __forceinline__ void warp_reduce_top2(float& bd1, int& bi1,
                                                 float& bd2, int& bi2) {
#pragma unroll
    for (int o = 16; o > 0; o >>= 1) {
        float e1 = __shfl_xor_sync(0xFFFFFFFFu, bd1, o);
        float e2 = __shfl_xor_sync(0xFFFFFFFFu, bd2, o);
        int j1 = __shfl_xor_sync(0xFFFFFFFFu, bi1, o);
        int j2 = __shfl_xor_sync(0xFFFFFFFFu, bi2, o);
        ins2(e1, j1, bd1, bi1, bd2, bi2);
        ins2(e2, j2, bd1, bi1, bd2, bi2);
    }
}

__device__ __forceinline__ float score(float qx, float qy, float qz, float q2,
                                       float4 P) {
    float dot2 = __fadd_rn(__fadd_rn(__fmul_rn(qx, P.x), __fmul_rn(qy, P.y)),
                           __fmul_rn(qz, P.z));
    return __fsub_rn(__fadd_rn(q2, P.w), dot2);
}

// ---------------------------------------------------------------------------
// K1 (launch 0): gathers + binning + histogram
// ---------------------------------------------------------------------------
__global__ void gather_kernel(const float* __restrict__ pc,
                              const float4* __restrict__ feats4,
                              const int* __restrict__ rnds,
                              float* __restrict__ out) {
    int i = blockIdx.x * blockDim.x + threadIdx.x;
    const int WF = BATCH * HALF * 8;
    const int WP = BATCH * HALF;

    if (i < WF) {
        int c = i & 7;
        int t = (i >> 3) & (HALF - 1);
        int b = i >> 16;
        int v = rnds[t];
        float4 val = feats4[(b * NPTS + v) * 8 + c];
        ((float4*)(out + OFF_VFEAT))[(b * HALF + t) * 8 + c] = val;
        return;
    }
    i -= WF;
    if (i < WP) {
        int t = i & (HALF - 1);
        int b = i >> 13;
        int v = rnds[t];
        int base = (b * NPTS + v) * 3;
        float x = pc[base + 0], y = pc[base + 1], z = pc[base + 2];
        int ob = OFF_VPC + (b * HALF + t) * 3;
        out[ob + 0] = x; out[ob + 1] = y; out[ob + 2] = z;
        g_valid[b][t] = make_float4(2.0f * x, 2.0f * y, 2.0f * z, sq3(x, y, z));
        int cid = cell_of(x, y, z);
        g_pcell[b][t] = cid;
        atomicAdd(&g_cnt[0][b][cid], 1);
        return;
    }
    i -= WP;
    if (i < WP) {
        int t = i & (HALF - 1);
        int b = i >> 13;
        int v = rnds[HALF + t];
        int base = (b * NPTS + v) * 3;
        float x = pc[base + 0], y = pc[base + 1], z = pc[base + 2];
        g_query[b][t] = make_float4(x, y, z, sq3(x, y, z));
        int cid = cell_of(x, y, z);
        g_qcell[b][t] = cid;
        atomicAdd(&g_cnt[1][b][cid], 1);
        return;
    }
    i -= WP;
    if (i < NPTS) out[OFF_RNDS + i] = (float)rnds[i];
}

// ---------------------------------------------------------------------------
// K2 (launch 1): exclusive scan via two-level warp shuffle scan
// ---------------------------------------------------------------------------
__global__ void __launch_bounds__(1024) scan_kernel() {
    int kind = blockIdx.x >> 2;
    int b = blockIdx.x & 3;
    const int CPT = NC / 1024;  // 4
    int tid = threadIdx.x;
    int lane = tid & 31;
    int wid = tid >> 5;

    int loc[CPT];
    int s = 0;
    const int* cnt = g_cnt[kind][b];
#pragma unroll
    for (int j = 0; j < CPT; ++j) { loc[j] = s; s += cnt[tid * CPT + j]; }

    int inc = s;
#pragma unroll
    for (int o = 1; o < 32; o <<= 1) {
        int v = __shfl_up_sync(0xFFFFFFFFu, inc, o);
        if (lane >= o) inc += v;
    }
    __shared__ int wsum[32];
    if (lane == 31) wsum[wid] = inc;
    __syncthreads();
    if (wid == 0) {
        int v = wsum[lane];
        int wi = v;
#pragma unroll
        for (int o = 1; o < 32; o <<= 1) {
            int u = __shfl_up_sync(0xFFFFFFFFu, wi, o);
            if (lane >= o) wi += u;
        }
        wsum[lane] = wi - v;
    }
    __syncthreads();
    int base = wsum[wid] + (inc - s);

    int* off_arr = g_off[kind][b];
    int* cur_arr = g_cur[kind][b];
#pragma unroll
    for (int j = 0; j < CPT; ++j) {
        int v = base + loc[j];
        off_arr[tid * CPT + j] = v;
        cur_arr[tid * CPT + j] = v;
    }
    if (tid == 1023) off_arr[NC] = base + s;
}

// ---------------------------------------------------------------------------
// K3 (launch 2): scatter into cell-sorted order
// ---------------------------------------------------------------------------
__global__ void scatter_kernel() {
    int i = blockIdx.x * blockDim.x + threadIdx.x;
    if (i >= 2 * BATCH * HALF) return;
    int kind = i >> 15;
    int b = (i >> 13) & (BATCH - 1);
    int t = i & (HALF - 1);
    if (kind == 0) {
        int cid = g_pcell[b][t];
        int pos = atomicAdd(&g_cur[0][b][cid], 1);
        g_spt[b][pos] = g_valid[b][t];
        g_sid[b][pos] = t;
    } else {
        int cid = g_qcell[b][t];
        int pos = atomicAdd(&g_cur[1][b][cid], 1);
        g_sq[b][pos] = g_query[b][t];
        g_sqid[b][pos] = t;
        g_sqc[b][pos] = cid;
    }
}

// ---------------------------------------------------------------------------
// K4 (launch 3 — the ncu-captured slot): warp-per-query KNN, R8 structure.
// Run-based cooperative box scan; lazy id loads; dedup-safe top-2; bounded
// brute-force fallback. Tail: re-zero g_cnt for the next graph replay (safe:
// nothing reads g_cnt after scan; next gather is stream-ordered after us).
// ---------------------------------------------------------------------------
template <int R>
__device__ __forceinline__ void scan_box(int qcx, int qcy, int qcz,
                                         float qx, float qy, float qz, float q2,
                                         const float4* __restrict__ pts,
                                         const int* __restrict__ ids,
                                         const int* __restrict__ offs,
                                         int lane,
                                         float& bd1, int& bi1,
                                         float& bd2, int& bi2) {
    const int NR = (2 * R + 1) * (2 * R + 1);
    int p0 = 0, len = 0;
    if (lane < NR) {
        int dy = lane % (2 * R + 1) - R;
        int dz = lane / (2 * R + 1) - R;
        int cy = qcy + dy, cz = qcz + dz;
        if (cy >= 0 && cy < GD && cz >= 0 && cz < GD) {
            int cx0 = max(qcx - R, 0), cx1 = min(qcx + R, GD - 1);
            int rowbase = (cz * GD + cy) * GD;
            p0 = __ldg(&offs[rowbase + cx0]);
            len = __ldg(&offs[rowbase + cx1 + 1]) - p0;
        }
    }
    // warp inclusive scan of len
    int inc = len;
#pragma unroll
    for (int o = 1; o < 32; o <<= 1) {
        int v = __shfl_up_sync(0xFFFFFFFFu, inc, o);
        if (lane >= o) inc += v;
    }
    int excl = inc - len;
    int T = __shfl_sync(0xFFFFFFFFu, inc, NR - 1);

    for (int base = 0; base < T; base += 32) {
        int c = base + lane;
        bool active = c < T;
        int cc = active ? c : (T - 1);
        // binary search: largest run k (k < NR) with excl_k <= cc
        int lo = 0;
#pragma unroll
        for (int step = 16; step > 0; step >>= 1) {
            int mid = lo + step;
            int v = __shfl_sync(0xFFFFFFFFu, excl, min(mid, 31));
            if (mid < NR && v <= cc) lo = mid;
        }
        int rp0 = __shfl_sync(0xFFFFFFFFu, p0, lo);
        int rex = __shfl_sync(0xFFFFFFFFu, excl, lo);
        int p = rp0 + (cc - rex);
        float4 P = pts[p];
        if (active) {
            float d2 = score(qx, qy, qz, q2, P);
            if (d2 <= bd2) {            // lazy id: only when insert is possible
                ins2(d2, ids[p], bd1, bi1, bd2, bi2);
            }
        }
    }
    warp_reduce_top2(bd1, bi1, bd2, bi2);
}

// warp-uniform: can any unvisited cell (outside box qc +- r) beat bd2?
__device__ __forceinline__ bool term_ok(int qcx, int qcy, int qcz, int r,
                                        float qx, float qy, float qz,
                                        float bd2, const float* sbnd) {
    const float INF = __int_as_float(0x7f800000);
    if (!(bd2 < INF)) return false;
    float lb = INF;
    if (qcx - r > 0)      lb = fminf(lb, qx - sbnd[qcx - r]);
    if (qcx + r < GD - 1) lb = fminf(lb, sbnd[qcx + r + 1] - qx);
    if (qcy - r > 0)      lb = fminf(lb, qy - sbnd[qcy - r]);
    if (qcy + r < GD - 1) lb = fminf(lb, sbnd[qcy + r + 1] - qy);
    if (qcz - r > 0)      lb = fminf(lb, qz - sbnd[qcz - r]);
    if (qcz + r < GD - 1) lb = fminf(lb, sbnd[qcz + r + 1] - qz);
    float lba = fmaxf(lb - 1e-5f, 0.0f);
    return lba * lba > bd2 * 1.001f + 1e-4f;
}

__global__ void __launch_bounds__(256) knn_kernel(float* __restrict__ out) {
    __shared__ float sbnd[GD + 1];
    if (threadIdx.x < GD + 1) sbnd[threadIdx.x] = c_bnd[threadIdx.x];
    __syncthreads();

    int w = (blockIdx.x * blockDim.x + threadIdx.x) >> 5;
    int lane = threadIdx.x & 31;
    int b = w >> 13;
    int s = w & (HALF - 1);

    float4 q = g_sq[b][s];
    int qi = g_sqid[b][s];
    int qc = g_sqc[b][s];
    const float qx = q.x, qy = q.y, qz = q.z, q2 = q.w;

    int qcx = qc & (GD - 1);
    int qcy = (qc >> 4) & (GD - 1);
    int qcz = qc >> 8;

    const float INF = __int_as_float(0x7f800000);
    float bd1 = INF, bd2 = INF;
    int bi1 = 0x7fffffff, bi2 = 0x7fffffff;

    const float4* __restrict__ pts = g_spt[b];
    const int* __restrict__ ids = g_sid[b];
    const int* __restrict__ offs = g_off[0][b];

    // Phase 1: 3x3x3 box as 9 contiguous runs
    scan_box<1>(qcx, qcy, qcz, qx, qy, qz, q2, pts, ids, offs, lane,
                bd1, bi1, bd2, bi2);

    if (!term_ok(qcx, qcy, qcz, 1, qx, qy, qz, bd2, sbnd)) {
        // Phase 2: 5x5x5 box as 25 runs (interior rescan deduped by id)
        scan_box<2>(qcx, qcy, qcz, qx, qy, qz, q2, pts, ids, offs, lane,
                    bd1, bi1, bd2, bi2);

        if (!term_ok(qcx, qcy, qcz, 2, qx, qy, qz, bd2, sbnd)) {
            // Phase 3: bounded fallback — full warp-parallel brute force
            for (int p = lane; p < HALF; p += 32) {
                float d2 = score(qx, qy, qz, q2, pts[p]);
                if (d2 <= bd2) ins2(d2, ids[p], bd1, bi1, bd2, bi2);
            }
            warp_reduce_top2(bd1, bi1, bd2, bi2);
        }
    }

    if (lane == 0) out[OFF_NIDX + (b << 13) + qi] = (float)bi2;

    // Tail: re-zero histograms for the next graph replay.
    // 4096 blocks x 8 ints == 2*BATCH*NC == 32768. No reader of g_cnt runs
    // after scan_kernel in this replay; next replay's gather is stream-ordered.
    if (threadIdx.x < 8) {
        ((int*)g_cnt)[blockIdx.x * 8 + threadIdx.x] = 0;
    }
}

// ---------------------------------------------------------------------------
extern "C" void kernel_launch(void* const* d_in, const int* in_sizes, int n_in,
                              void* d_out, int out_size) {
    const float*  pc    = (const float*)d_in[0];
    const float4* feats = (const float4*)d_in[1];
    const int*    rnds  = (const int*)d_in[2];
    float*        out   = (float*)d_out;
    (void)in_sizes; (void)n_in; (void)out_size;

    const int total = BATCH * HALF * 8 + 2 * BATCH * HALF + NPTS;  // 344064
    gather_kernel<<<total / 256, 256>>>(pc, feats, rnds, out);

    scan_kernel<<<2 * BATCH, 1024>>>();
    scatter_kernel<<<(2 * BATCH * HALF + 255) / 256, 256>>>();

    // one warp per query: 32768 warps = 4096 blocks of 256 threads
    knn_kernel<<<BATCH * HALF * 32 / 256, 256>>>(out);
}